// round 8
// baseline (speedup 1.0000x reference)
#include <cuda_runtime.h>
#include <cuda_bf16.h>
#include <cstdint>
#include <math.h>

#define TT 60
#define BB 64
#define SS 256
#define DD 1024
#define HH 20
#define MTOT (BB*TT)   // 3840 rows of q

// ---- scratch (static device globals) ----
__device__ float g_w[TT][HH];                    // history softmax weights
__device__ float g_attn_w[TT*BB*SS];             // windowed attention [(t*B+b)*S+s]
__device__ __nv_bfloat16 g_Ah[MTOT*DD];          // q split hi   [m=b*T+t][k]
__device__ __nv_bfloat16 g_Al[MTOT*DD];          // q split lo
__device__ __nv_bfloat16 g_BTh[DD*DD];           // Wq^T split hi [n][k]
__device__ __nv_bfloat16 g_BTl[DD*DD];           // Wq^T split lo
__device__ __nv_bfloat16 g_Gh[MTOT*DD];          // (q@Wq) split hi [m][d]
__device__ __nv_bfloat16 g_Gl[MTOT*DD];          // (q@Wq) split lo
__device__ float g_Eq0[TT*BB*SS];                // e . (qWq)  [(t*B+b)*S+s]
__device__ float g_Eq[TT*BB*SS];                 // windowed Eq0
__device__ float g_rp[TT*BB];                    // remove_prob
__device__ float g_ap[TT*BB];                    // add_prob
__device__ float g_lc[TT*BB];                    // sum_s attn_w*eW2
__device__ float g_eW1[BB*SS];                   // e . Wn[:D]
__device__ float g_eW2[BB*SS];                   // e . Wn[D:]
__device__ __nv_bfloat16 g_Wh[BB*64*SS];         // sel weights split hi [b][t(pad64)][s]
__device__ __nv_bfloat16 g_Wl[BB*64*SS];         // sel weights split lo

__device__ __forceinline__ float sigf(float x){ return 1.0f/(1.0f+expf(-x)); }
__device__ __forceinline__ void split1(float x, __nv_bfloat16& h, __nv_bfloat16& l){
    h = __float2bfloat16(x);
    l = __float2bfloat16(x - __bfloat162float(h));
}
__device__ __forceinline__ uint32_t s2u(const void* p){
    return (uint32_t)__cvta_generic_to_shared(p);
}

#define MMA_BF16(d, a, b0, b1) asm volatile( \
  "mma.sync.aligned.m16n8k16.row.col.f32.bf16.bf16.f32 " \
  "{%0,%1,%2,%3},{%4,%5,%6,%7},{%8,%9},{%0,%1,%2,%3};\n" \
  : "+f"(d[0]), "+f"(d[1]), "+f"(d[2]), "+f"(d[3]) \
  : "r"(a[0]), "r"(a[1]), "r"(a[2]), "r"(a[3]), "r"(b0), "r"(b1))

#define LDSM_X4(r, addr) asm volatile( \
  "ldmatrix.sync.aligned.m8n8.x4.shared.b16 {%0,%1,%2,%3},[%4];\n" \
  : "=r"((r)[0]), "=r"((r)[1]), "=r"((r)[2]), "=r"((r)[3]) : "r"(addr))

#define CP16(saddr, gptr) asm volatile( \
  "cp.async.ca.shared.global [%0], [%1], 16;\n" :: "r"(saddr), "l"(gptr))

// ---- step-weight table ----
__global__ void k_weights(){
    int i = threadIdx.x;
    if (i >= TT) return;
    int k = min(i+1, HH);
    float Z = 0.f;
    for (int j = 0; j < k; j++) Z += expf((20.f - (float)j) / 20.f);
    for (int j = 0; j < HH; j++)
        g_w[i][j] = (j < k) ? expf((20.f - (float)j) / 20.f) / Z : 0.f;
}

// ---- transpose + split Wq: [k][n] -> WqT [n][k] hi/lo ----
__global__ void k_split_Wq(const float* __restrict__ Wq){
    __shared__ float tile[32][33];
    int k0 = blockIdx.y*32, n0 = blockIdx.x*32;
    int tx = threadIdx.x, ty = threadIdx.y;  // (32,8)
    #pragma unroll
    for (int i = 0; i < 32; i += 8)
        tile[ty+i][tx] = Wq[(size_t)(k0+ty+i)*DD + n0+tx];
    __syncthreads();
    #pragma unroll
    for (int i = 0; i < 32; i += 8){
        float x = tile[tx][ty+i];
        __nv_bfloat16 h, l; split1(x, h, l);
        size_t o = (size_t)(n0+ty+i)*DD + k0+tx;
        g_BTh[o] = h;
        g_BTl[o] = l;
    }
}

// ---- gates rp/ap[t,b] + q bf16 split: one warp per (t,b) ----
__global__ void k_gates(const float* __restrict__ q, const float* __restrict__ Wr,
                        const float* __restrict__ br, const float* __restrict__ Wa,
                        const float* __restrict__ ba){
    int w = (blockIdx.x*blockDim.x + threadIdx.x) >> 5;
    int lane = threadIdx.x & 31;
    if (w >= TT*BB) return;
    int t = w / BB, b = w % BB;
    const size_t qoff = (size_t)(b*TT + t)*DD;
    const float* qr = q + qoff;
    float s1 = 0.f, s2 = 0.f;
    for (int d = lane*4; d < DD; d += 128){
        float4 qv = *(const float4*)(qr + d);
        float4 r4 = *(const float4*)(Wr + d);
        float4 a4 = *(const float4*)(Wa + d);
        s1 += qv.x*r4.x + qv.y*r4.y + qv.z*r4.z + qv.w*r4.w;
        s2 += qv.x*a4.x + qv.y*a4.y + qv.z*a4.z + qv.w*a4.w;
        __nv_bfloat16 h0,l0,h1,l1,h2,l2,h3,l3;
        split1(qv.x,h0,l0); split1(qv.y,h1,l1); split1(qv.z,h2,l2); split1(qv.w,h3,l3);
        __nv_bfloat162 hh0; hh0.x=h0; hh0.y=h1;
        __nv_bfloat162 hh1; hh1.x=h2; hh1.y=h3;
        __nv_bfloat162 ll0; ll0.x=l0; ll0.y=l1;
        __nv_bfloat162 ll1; ll1.x=l2; ll1.y=l3;
        *(__nv_bfloat162*)&g_Ah[qoff + d]     = hh0;
        *(__nv_bfloat162*)&g_Ah[qoff + d + 2] = hh1;
        *(__nv_bfloat162*)&g_Al[qoff + d]     = ll0;
        *(__nv_bfloat162*)&g_Al[qoff + d + 2] = ll1;
    }
    for (int o = 16; o; o >>= 1){
        s1 += __shfl_xor_sync(0xffffffffu, s1, o);
        s2 += __shfl_xor_sync(0xffffffffu, s2, o);
    }
    if (lane == 0){
        g_rp[w] = sigf(s1 + br[0]);
        g_ap[w] = sigf(s2 + ba[0]);
    }
}

// ---- windowed attn + fused lc reduce: one block per (t,b), thread = s ----
__global__ void k_window_attn_lc(const float* __restrict__ at){
    const int blk = blockIdx.x;           // = t*BB + b
    const int t = blk / BB, b = blk % BB;
    const int s = threadIdx.x;
    const int lane = s & 31, warp = s >> 5;
    int k = min(t+1, HH);
    float acc = 0.f;
    for (int j = 0; j < k; j++)
        acc = fmaf(g_w[t][j], at[(size_t)(b*TT + (t-j))*SS + s], acc);
    g_attn_w[(size_t)blk*SS + s] = acc;
    float v = acc * g_eW2[b*SS + s];
    __shared__ float red[8];
    for (int o = 16; o; o >>= 1) v += __shfl_xor_sync(0xffffffffu, v, o);
    if (lane == 0) red[warp] = v;
    __syncthreads();
    if (warp == 0){
        float x = (lane < 8) ? red[lane] : 0.f;
        for (int o = 4; o; o >>= 1) x += __shfl_xor_sync(0xffffffffu, x, o);
        if (lane == 0) g_lc[blk] = x;
    }
}

// ---- tensor-core GEMM: G = q @ Wq, 4 warps x (64x64) tiles, cp.async 2-stage ----
// dynamic smem: 2 stages x 4 arrays x [128 rows x 40 bf16 (32 data + 8 pad)]
#define GARR   10240   // bytes per array per stage (128*40*2)
#define GSTAGE 40960   // bytes per stage
__global__ __launch_bounds__(128, 2) void k_gemm(){
    extern __shared__ __align__(16) unsigned char dsm[];
    const int tid = threadIdx.x;
    const int m0 = blockIdx.y * 128;
    const int n0 = blockIdx.x * 128;
    const int w = tid >> 5, lane = tid & 31;
    const int wm = (w & 1) * 64;
    const int wn = (w >> 1) * 64;

    const int rsA = (lane & 7) + ((lane >> 3) & 1) * 8;
    const int kbA = ((lane >> 4) & 1) * 16;
    const int rsB = (lane & 7) + ((lane >> 4) & 1) * 8;
    const int kbB = ((lane >> 3) & 1) * 16;

    const uint32_t sbase = s2u(dsm);
    const uint32_t aH0 = sbase + (uint32_t)(wm + rsA)*80 + kbA;
    const uint32_t aL0 = aH0 + GARR;
    const uint32_t bH0 = sbase + 2*GARR + (uint32_t)(wn + rsB)*80 + kbB;
    const uint32_t bL0 = bH0 + GARR;

    // staging: thread t copies row t (cols k0..k0+31) of each of the 4 arrays
    const size_t aRow = (size_t)(m0 + tid)*DD;
    const size_t bRow = (size_t)(n0 + tid)*DD;
    const uint32_t stRow = sbase + (uint32_t)tid*80;

    float acc[4][8][4] = {};

    // prologue: issue stage 0
    #pragma unroll
    for (int j = 0; j < 4; j++){
        CP16(stRow            + j*16, &g_Ah[aRow + j*8]);
        CP16(stRow +   GARR   + j*16, &g_Al[aRow + j*8]);
        CP16(stRow + 2*GARR   + j*16, &g_BTh[bRow + j*8]);
        CP16(stRow + 3*GARR   + j*16, &g_BTl[bRow + j*8]);
    }
    asm volatile("cp.async.commit_group;\n" ::: "memory");

    const int NIT = DD/32;   // 32 chunks
    for (int it = 0; it < NIT; it++){
        const uint32_t so = (uint32_t)(it & 1) * GSTAGE;
        if (it + 1 < NIT){
            const int k0 = (it+1)*32;
            const uint32_t sn = (uint32_t)((it+1) & 1) * GSTAGE;
            #pragma unroll
            for (int j = 0; j < 4; j++){
                CP16(stRow + sn            + j*16, &g_Ah[aRow + k0 + j*8]);
                CP16(stRow + sn +   GARR   + j*16, &g_Al[aRow + k0 + j*8]);
                CP16(stRow + sn + 2*GARR   + j*16, &g_BTh[bRow + k0 + j*8]);
                CP16(stRow + sn + 3*GARR   + j*16, &g_BTl[bRow + k0 + j*8]);
            }
            asm volatile("cp.async.commit_group;\n" ::: "memory");
            asm volatile("cp.async.wait_group 1;\n" ::: "memory");
        } else {
            asm volatile("cp.async.wait_group 0;\n" ::: "memory");
        }
        __syncthreads();
        #pragma unroll
        for (int ks = 0; ks < 2; ks++){
            const int ksb = ks * 32;   // bytes
            unsigned ah[4][4], al_[4][4];
            #pragma unroll
            for (int mf = 0; mf < 4; mf++){
                LDSM_X4(ah[mf],  aH0 + so + mf*16*80 + ksb);
                LDSM_X4(al_[mf], aL0 + so + mf*16*80 + ksb);
            }
            #pragma unroll
            for (int p = 0; p < 4; p++){
                unsigned bh[4], bl[4];
                LDSM_X4(bh, bH0 + so + p*16*80 + ksb);
                LDSM_X4(bl, bL0 + so + p*16*80 + ksb);
                #pragma unroll
                for (int mf = 0; mf < 4; mf++){
                    MMA_BF16(acc[mf][2*p],   ah[mf],  bh[0], bh[1]);
                    MMA_BF16(acc[mf][2*p],   ah[mf],  bl[0], bl[1]);
                    MMA_BF16(acc[mf][2*p],   al_[mf], bh[0], bh[1]);
                    MMA_BF16(acc[mf][2*p+1], ah[mf],  bh[2], bh[3]);
                    MMA_BF16(acc[mf][2*p+1], ah[mf],  bl[2], bl[3]);
                    MMA_BF16(acc[mf][2*p+1], al_[mf], bh[2], bh[3]);
                }
            }
        }
        __syncthreads();
    }
    const int lr4 = lane >> 2;
    const int lc2 = (lane & 3) * 2;
    #pragma unroll
    for (int mf = 0; mf < 4; mf++)
        #pragma unroll
        for (int nt = 0; nt < 8; nt++){
            int row = m0 + wm + mf*16 + lr4;
            int col = n0 + wn + nt*8 + lc2;
            #pragma unroll
            for (int rr = 0; rr < 2; rr++){
                float x = acc[mf][nt][rr*2], y = acc[mf][nt][rr*2+1];
                __nv_bfloat16 hx,lx,hy,ly;
                split1(x,hx,lx); split1(y,hy,ly);
                __nv_bfloat162 hh; hh.x=hx; hh.y=hy;
                __nv_bfloat162 ll; ll.x=lx; ll.y=ly;
                size_t o = (size_t)(row + rr*8)*DD + col;
                *(__nv_bfloat162*)&g_Gh[o] = hh;
                *(__nv_bfloat162*)&g_Gl[o] = ll;
            }
        }
}

// ---- tensor-core Eq0 + fused eW: per-b C[s,t] = e[b,s,:].G[b,t,:] ----
__global__ __launch_bounds__(256) void k_eq0(const float* __restrict__ e,
                                             const float* __restrict__ Wn){
    __shared__ __align__(16) __nv_bfloat16 sAh[64][72], sAl[64][72];
    __shared__ __align__(16) __nv_bfloat16 sBh[64][72], sBl[64][72];
    const int tid = threadIdx.x;
    const int b = blockIdx.y;
    const int s0 = blockIdx.x * 64;
    const int wid = tid >> 5, lane = tid & 31;
    const int wm = (wid & 1) * 32;
    const int wn = (wid >> 1) * 16;
    const int lr = tid >> 2;            // staging row 0..63
    const int kq = (tid & 3) * 16;      // k offset

    const int rsA = (lane & 7) + ((lane >> 3) & 1) * 8;
    const int kbA = ((lane >> 4) & 1) * 16;
    const int rsB = (lane & 7) + ((lane >> 4) & 1) * 8;
    const int kbB = ((lane >> 3) & 1) * 16;
    const uint32_t aH = s2u(&sAh[wm + rsA][0]) + kbA;
    const uint32_t aL = s2u(&sAl[wm + rsA][0]) + kbA;
    const uint32_t bH = s2u(&sBh[wn + rsB][0]) + kbB;
    const uint32_t bL = s2u(&sBl[wn + rsB][0]) + kbB;

    const size_t aRow = (size_t)(b*SS + s0 + lr)*DD;
    const bool bv = lr < TT;
    const size_t bRow = (size_t)(b*TT + (bv ? lr : 0))*DD;

    float acc[2][2][4] = {};
    float s1 = 0.f, s2 = 0.f;   // fused eW dots for row lr (partial over kq)

    for (int k0 = 0; k0 < DD; k0 += 64){
        float4 av[4];
        #pragma unroll
        for (int q4 = 0; q4 < 4; q4++){
            av[q4] = *(const float4*)&e[aRow + k0 + kq + q4*4];
            float4 w1 = *(const float4*)&Wn[k0 + kq + q4*4];
            float4 w2 = *(const float4*)&Wn[DD + k0 + kq + q4*4];
            s1 += av[q4].x*w1.x + av[q4].y*w1.y + av[q4].z*w1.z + av[q4].w*w1.w;
            s2 += av[q4].x*w2.x + av[q4].y*w2.y + av[q4].z*w2.z + av[q4].w*w2.w;
        }
        uint4 z = make_uint4(0,0,0,0);
        uint4 gh0 = bv ? *(const uint4*)&g_Gh[bRow + k0 + kq]     : z;
        uint4 gh1 = bv ? *(const uint4*)&g_Gh[bRow + k0 + kq + 8] : z;
        uint4 gl0 = bv ? *(const uint4*)&g_Gl[bRow + k0 + kq]     : z;
        uint4 gl1 = bv ? *(const uint4*)&g_Gl[bRow + k0 + kq + 8] : z;
        __syncthreads();
        #pragma unroll
        for (int q4 = 0; q4 < 4; q4++){
            float vv[4] = {av[q4].x, av[q4].y, av[q4].z, av[q4].w};
            #pragma unroll
            for (int u = 0; u < 4; u += 2){
                __nv_bfloat16 h0,l0,h1,l1;
                split1(vv[u],h0,l0); split1(vv[u+1],h1,l1);
                __nv_bfloat162 hh; hh.x=h0; hh.y=h1;
                __nv_bfloat162 ll; ll.x=l0; ll.y=l1;
                *(__nv_bfloat162*)&sAh[lr][kq + q4*4 + u] = hh;
                *(__nv_bfloat162*)&sAl[lr][kq + q4*4 + u] = ll;
            }
        }
        *(uint4*)&sBh[lr][kq]     = gh0;
        *(uint4*)&sBh[lr][kq + 8] = gh1;
        *(uint4*)&sBl[lr][kq]     = gl0;
        *(uint4*)&sBl[lr][kq + 8] = gl1;
        __syncthreads();
        #pragma unroll
        for (int ks = 0; ks < 64; ks += 16){
            const int ksb = ks * 2;
            unsigned ah[2][4], al_[2][4], bh[4], bl[4];
            LDSM_X4(ah[0],  aH + ksb);
            LDSM_X4(ah[1],  aH + 16*144 + ksb);
            LDSM_X4(al_[0], aL + ksb);
            LDSM_X4(al_[1], aL + 16*144 + ksb);
            LDSM_X4(bh, bH + ksb);
            LDSM_X4(bl, bL + ksb);
            #pragma unroll
            for (int mf = 0; mf < 2; mf++){
                MMA_BF16(acc[mf][0], ah[mf],  bh[0], bh[1]);
                MMA_BF16(acc[mf][0], ah[mf],  bl[0], bl[1]);
                MMA_BF16(acc[mf][0], al_[mf], bh[0], bh[1]);
                MMA_BF16(acc[mf][1], ah[mf],  bh[2], bh[3]);
                MMA_BF16(acc[mf][1], ah[mf],  bl[2], bl[3]);
                MMA_BF16(acc[mf][1], al_[mf], bh[2], bh[3]);
            }
        }
        __syncthreads();
    }
    // fused eW reduction: 4 threads share row lr (consecutive lanes)
    s1 += __shfl_xor_sync(0xffffffffu, s1, 1);
    s1 += __shfl_xor_sync(0xffffffffu, s1, 2);
    s2 += __shfl_xor_sync(0xffffffffu, s2, 1);
    s2 += __shfl_xor_sync(0xffffffffu, s2, 2);
    if ((tid & 3) == 0){
        g_eW1[b*SS + s0 + lr] = s1;
        g_eW2[b*SS + s0 + lr] = s2;
    }
    const int lr4 = lane >> 2;
    const int lc2 = (lane & 3) * 2;
    #pragma unroll
    for (int mf = 0; mf < 2; mf++)
        #pragma unroll
        for (int nf = 0; nf < 2; nf++){
            int s = s0 + wm + mf*16 + lr4;
            int t0 = wn + nf*8 + lc2;
            if (t0 < TT){
                g_Eq0[((size_t)t0*BB + b)*SS + s]       = acc[mf][nf][0];
                g_Eq0[((size_t)t0*BB + b)*SS + s + 8]   = acc[mf][nf][2];
            }
            if (t0 + 1 < TT){
                g_Eq0[((size_t)(t0+1)*BB + b)*SS + s]     = acc[mf][nf][1];
                g_Eq0[((size_t)(t0+1)*BB + b)*SS + s + 8] = acc[mf][nf][3];
            }
        }
}

// ---- 20-tap window over Eq0 -> Eq ----
__global__ void k_window_eq(){
    int idx = blockIdx.x*blockDim.x + threadIdx.x;
    if (idx >= TT*BB*SS) return;
    int s = idx % SS; int b = (idx / SS) % BB; int t = idx / (SS*BB);
    int k = min(t+1, HH);
    float acc = 0.f;
    for (int j = 0; j < k; j++)
        acc = fmaf(g_w[t][j], g_Eq0[((size_t)(t-j)*BB + b)*SS + s], acc);
    g_Eq[idx] = acc;
}

// ---- scalar recurrence; emits split+transposed sel weights [b][t][s] ----
__global__ void k_recur(const float* __restrict__ at, const float* __restrict__ bn){
    int idx = blockIdx.x*blockDim.x + threadIdx.x;
    if (idx >= BB*SS) return;
    const int b = idx / SS, s = idx % SS;
    float add0 = (s < 50) ? 1.f - (float)(s+1)*0.02f : 0.f;
    float g = add0, a = add0;
    const float ew1 = g_eW1[idx];
    const float bnv = bn[0];
    for (int t = 0; t < TT; t++){
        int base = (t*BB + b)*SS + s;
        float aw  = g_attn_w[base];
        float eq  = g_Eq[base];
        float atv = at[(size_t)(b*TT + t)*SS + s];
        float w = atv * g;                          // pre-update g
        __nv_bfloat16 h, l; split1(w, h, l);
        size_t wo = ((size_t)(b*64 + t))*SS + s;
        g_Wh[wo] = h; g_Wl[wo] = l;
        float rp = g_rp[t*BB + b], ap = g_ap[t*BB + b];
        float lc = g_lc[t*BB + b];
        float sim = sigf(g * eq);
        float nxt = sigf(ew1 + lc + bnv);
        float c2  = (1.f - a) * ap * nxt;
        g = g * (1.f - rp * aw * sim) + c2;
        a = a + c2;
    }
    __nv_bfloat16 zz = __float2bfloat16(0.f);
    for (int t = TT; t < 64; t++){
        size_t wo = ((size_t)(b*64 + t))*SS + s;
        g_Wh[wo] = zz; g_Wl[wo] = zz;
    }
}

// ---- tensor-core sel: per-b out[t,d] = sum_s W[t,s]*e[s,d] ----
__global__ __launch_bounds__(256) void k_sel(const float* __restrict__ e, float* __restrict__ out){
    __shared__ __align__(16) __nv_bfloat16 sWh[64][40], sWl[64][40];
    __shared__ __align__(16) __nv_bfloat16 sEh[128][40], sEl[128][40];
    const int tid = threadIdx.x;
    const int b = blockIdx.y;
    const int d0 = blockIdx.x * 128;
    const int wid = tid >> 5, lane = tid & 31;
    const int wm = (wid & 1) * 32;
    const int wn = (wid >> 1) * 32;
    // W staging (threads < 128): row wr, k group
    const int wr = tid >> 1, wkg = (tid & 1) * 16;
    // E staging (all 256): row er (s_local), col group cg
    const int er = tid & 31, cg = tid >> 5;

    const int rsA = (lane & 7) + ((lane >> 3) & 1) * 8;
    const int kbA = ((lane >> 4) & 1) * 16;
    const int rsB = (lane & 7) + ((lane >> 4) & 1) * 8;
    const int kbB = ((lane >> 3) & 1) * 16;
    const uint32_t aH = s2u(&sWh[wm + rsA][0]) + kbA;
    const uint32_t aL = s2u(&sWl[wm + rsA][0]) + kbA;
    const uint32_t bH = s2u(&sEh[wn + rsB][0]) + kbB;
    const uint32_t bL = s2u(&sEl[wn + rsB][0]) + kbB;

    float acc[2][4][4] = {};

    for (int s0 = 0; s0 < SS; s0 += 32){
        uint4 wv0, wv1, wl0, wl1;
        if (tid < 128){
            size_t o = ((size_t)(b*64 + wr))*SS + s0 + wkg;
            wv0 = *(const uint4*)&g_Wh[o];
            wv1 = *(const uint4*)&g_Wh[o + 8];
            wl0 = *(const uint4*)&g_Wl[o];
            wl1 = *(const uint4*)&g_Wl[o + 8];
        }
        float4 ev[4];
        #pragma unroll
        for (int q4 = 0; q4 < 4; q4++)
            ev[q4] = *(const float4*)&e[(size_t)(b*SS + s0 + er)*DD + d0 + cg*16 + q4*4];
        __syncthreads();
        if (tid < 128){
            *(uint4*)&sWh[wr][wkg]     = wv0;
            *(uint4*)&sWh[wr][wkg + 8] = wv1;
            *(uint4*)&sWl[wr][wkg]     = wl0;
            *(uint4*)&sWl[wr][wkg + 8] = wl1;
        }
        #pragma unroll
        for (int q4 = 0; q4 < 4; q4++){
            float vv[4] = {ev[q4].x, ev[q4].y, ev[q4].z, ev[q4].w};
            #pragma unroll
            for (int u = 0; u < 4; u++){
                __nv_bfloat16 h, l; split1(vv[u], h, l);
                int d_local = cg*16 + q4*4 + u;
                sEh[d_local][er] = h;
                sEl[d_local][er] = l;
            }
        }
        __syncthreads();
        #pragma unroll
        for (int ks = 0; ks < 32; ks += 16){
            const int ksb = ks * 2;
            unsigned ah[2][4], al_[2][4];
            LDSM_X4(ah[0],  aH + ksb);
            LDSM_X4(ah[1],  aH + 16*80 + ksb);
            LDSM_X4(al_[0], aL + ksb);
            LDSM_X4(al_[1], aL + 16*80 + ksb);
            #pragma unroll
            for (int p = 0; p < 2; p++){
                unsigned bh[4], bl[4];
                LDSM_X4(bh, bH + p*16*80 + ksb);
                LDSM_X4(bl, bL + p*16*80 + ksb);
                #pragma unroll
                for (int mf = 0; mf < 2; mf++){
                    MMA_BF16(acc[mf][2*p],   ah[mf],  bh[0], bh[1]);
                    MMA_BF16(acc[mf][2*p],   ah[mf],  bl[0], bl[1]);
                    MMA_BF16(acc[mf][2*p],   al_[mf], bh[0], bh[1]);
                    MMA_BF16(acc[mf][2*p+1], ah[mf],  bh[2], bh[3]);
                    MMA_BF16(acc[mf][2*p+1], ah[mf],  bl[2], bl[3]);
                    MMA_BF16(acc[mf][2*p+1], al_[mf], bh[2], bh[3]);
                }
            }
        }
        __syncthreads();
    }
    const int lr4 = lane >> 2;
    const int lc2 = (lane & 3) * 2;
    #pragma unroll
    for (int mf = 0; mf < 2; mf++)
        #pragma unroll
        for (int nf = 0; nf < 4; nf++){
            int d = d0 + wn + nf*8 + lc2;
            #pragma unroll
            for (int rr = 0; rr < 2; rr++){
                int t = wm + mf*16 + lr4 + rr*8;
                if (t < TT){
                    float2 v = make_float2(acc[mf][nf][rr*2], acc[mf][nf][rr*2+1]);
                    *(float2*)&out[((size_t)b*TT + t)*DD + d] = v;
                }
            }
        }
}

extern "C" void kernel_launch(void* const* d_in, const int* in_sizes, int n_in,
                              void* d_out, int out_size){
    const float* e  = (const float*)d_in[0];
    const float* q  = (const float*)d_in[1];
    const float* at = (const float*)d_in[2];
    const float* Wr = (const float*)d_in[3];
    const float* br = (const float*)d_in[4];
    const float* Wa = (const float*)d_in[5];
    const float* ba = (const float*)d_in[6];
    const float* Wq = (const float*)d_in[7];
    const float* Wn = (const float*)d_in[8];
    const float* bn = (const float*)d_in[9];
    float* out = (float*)d_out;

    static int smem_set = 0;
    if (!smem_set){
        cudaFuncSetAttribute(k_gemm, cudaFuncAttributeMaxDynamicSharedMemorySize, 2*GSTAGE);
        smem_set = 1;
    }

    k_weights<<<1, 64>>>();
    { dim3 gw(32, 32); k_split_Wq<<<gw, dim3(32, 8)>>>(Wq); }
    k_gates<<<(TT*BB*32 + 255)/256, 256>>>(q, Wr, br, Wa, ba);
    { dim3 gg(DD/128, MTOT/128); k_gemm<<<gg, 128, 2*GSTAGE>>>(); }
    { dim3 ge(SS/64, BB);        k_eq0<<<ge, 256>>>(e, Wn); }
    k_window_attn_lc<<<TT*BB, SS>>>(at);
    k_window_eq<<<(TT*BB*SS + 255)/256, 256>>>();
    k_recur<<<(BB*SS + 255)/256, 256>>>(at, bn);
    { dim3 gs(DD/128, BB);       k_sel<<<gs, 256>>>(e, out); }
}

// round 12
// speedup vs baseline: 1.1100x; 1.1100x over previous
#include <cuda_runtime.h>
#include <cuda_bf16.h>
#include <cstdint>
#include <math.h>

#define TT 60
#define BB 64
#define SS 256
#define DD 1024
#define HH 20
#define MTOT (BB*TT)   // 3840 rows of q

// ---- scratch (static device globals) ----
__device__ float g_w[TT][HH];                    // history softmax weights
__device__ float g_attn_w[TT*BB*SS];             // windowed attention [(t*B+b)*S+s]
__device__ __nv_bfloat16 g_Ah[MTOT*DD];          // q split hi   [m=b*T+t][k]
__device__ __nv_bfloat16 g_Al[MTOT*DD];          // q split lo
__device__ __nv_bfloat16 g_BTh[DD*DD];           // Wq^T split hi [n][k]
__device__ __nv_bfloat16 g_BTl[DD*DD];           // Wq^T split lo
__device__ __nv_bfloat16 g_Gh[MTOT*DD];          // (q@Wq) split hi [m][d]
__device__ __nv_bfloat16 g_Gl[MTOT*DD];          // (q@Wq) split lo
__device__ float g_Eq0[TT*BB*SS];                // e . (qWq)  [(t*B+b)*S+s]
__device__ float g_Eq[TT*BB*SS];                 // windowed Eq0
__device__ float g_rp[TT*BB];                    // remove_prob
__device__ float g_ap[TT*BB];                    // add_prob
__device__ float g_lc[TT*BB];                    // sum_s attn_w*eW2
__device__ float g_eW1[BB*SS];                   // e . Wn[:D]
__device__ float g_eW2[BB*SS];                   // e . Wn[D:]
__device__ __nv_bfloat16 g_Wh[BB*64*SS];         // sel weights split hi [b][t(pad64)][s]
__device__ __nv_bfloat16 g_Wl[BB*64*SS];         // sel weights split lo

__device__ __forceinline__ float sigf(float x){ return 1.0f/(1.0f+expf(-x)); }
__device__ __forceinline__ void split1(float x, __nv_bfloat16& h, __nv_bfloat16& l){
    h = __float2bfloat16(x);
    l = __float2bfloat16(x - __bfloat162float(h));
}
__device__ __forceinline__ uint32_t s2u(const void* p){
    return (uint32_t)__cvta_generic_to_shared(p);
}

#define MMA_BF16(d, a, b0, b1) asm volatile( \
  "mma.sync.aligned.m16n8k16.row.col.f32.bf16.bf16.f32 " \
  "{%0,%1,%2,%3},{%4,%5,%6,%7},{%8,%9},{%0,%1,%2,%3};\n" \
  : "+f"(d[0]), "+f"(d[1]), "+f"(d[2]), "+f"(d[3]) \
  : "r"(a[0]), "r"(a[1]), "r"(a[2]), "r"(a[3]), "r"(b0), "r"(b1))

#define LDSM_X4(r, addr) asm volatile( \
  "ldmatrix.sync.aligned.m8n8.x4.shared.b16 {%0,%1,%2,%3},[%4];\n" \
  : "=r"((r)[0]), "=r"((r)[1]), "=r"((r)[2]), "=r"((r)[3]) : "r"(addr))

#define CP16(saddr, gptr) asm volatile( \
  "cp.async.ca.shared.global [%0], [%1], 16;\n" :: "r"(saddr), "l"(gptr))

// ---- step-weight table ----
__global__ void k_weights(){
    int i = threadIdx.x;
    if (i >= TT) return;
    int k = min(i+1, HH);
    float Z = 0.f;
    for (int j = 0; j < k; j++) Z += expf((20.f - (float)j) / 20.f);
    for (int j = 0; j < HH; j++)
        g_w[i][j] = (j < k) ? expf((20.f - (float)j) / 20.f) / Z : 0.f;
}

// ---- transpose + split Wq: [k][n] -> WqT [n][k] hi/lo ----
__global__ void k_split_Wq(const float* __restrict__ Wq){
    __shared__ float tile[32][33];
    int k0 = blockIdx.y*32, n0 = blockIdx.x*32;
    int tx = threadIdx.x, ty = threadIdx.y;  // (32,8)
    #pragma unroll
    for (int i = 0; i < 32; i += 8)
        tile[ty+i][tx] = Wq[(size_t)(k0+ty+i)*DD + n0+tx];
    __syncthreads();
    #pragma unroll
    for (int i = 0; i < 32; i += 8){
        float x = tile[tx][ty+i];
        __nv_bfloat16 h, l; split1(x, h, l);
        size_t o = (size_t)(n0+ty+i)*DD + k0+tx;
        g_BTh[o] = h;
        g_BTl[o] = l;
    }
}

// ---- gates rp/ap[t,b] + q bf16 split: one warp per (t,b) ----
__global__ void k_gates(const float* __restrict__ q, const float* __restrict__ Wr,
                        const float* __restrict__ br, const float* __restrict__ Wa,
                        const float* __restrict__ ba){
    int w = (blockIdx.x*blockDim.x + threadIdx.x) >> 5;
    int lane = threadIdx.x & 31;
    if (w >= TT*BB) return;
    int t = w / BB, b = w % BB;
    const size_t qoff = (size_t)(b*TT + t)*DD;
    const float* qr = q + qoff;
    float s1 = 0.f, s2 = 0.f;
    for (int d = lane*4; d < DD; d += 128){
        float4 qv = *(const float4*)(qr + d);
        float4 r4 = *(const float4*)(Wr + d);
        float4 a4 = *(const float4*)(Wa + d);
        s1 += qv.x*r4.x + qv.y*r4.y + qv.z*r4.z + qv.w*r4.w;
        s2 += qv.x*a4.x + qv.y*a4.y + qv.z*a4.z + qv.w*a4.w;
        __nv_bfloat16 h0,l0,h1,l1,h2,l2,h3,l3;
        split1(qv.x,h0,l0); split1(qv.y,h1,l1); split1(qv.z,h2,l2); split1(qv.w,h3,l3);
        __nv_bfloat162 hh0; hh0.x=h0; hh0.y=h1;
        __nv_bfloat162 hh1; hh1.x=h2; hh1.y=h3;
        __nv_bfloat162 ll0; ll0.x=l0; ll0.y=l1;
        __nv_bfloat162 ll1; ll1.x=l2; ll1.y=l3;
        *(__nv_bfloat162*)&g_Ah[qoff + d]     = hh0;
        *(__nv_bfloat162*)&g_Ah[qoff + d + 2] = hh1;
        *(__nv_bfloat162*)&g_Al[qoff + d]     = ll0;
        *(__nv_bfloat162*)&g_Al[qoff + d + 2] = ll1;
    }
    for (int o = 16; o; o >>= 1){
        s1 += __shfl_xor_sync(0xffffffffu, s1, o);
        s2 += __shfl_xor_sync(0xffffffffu, s2, o);
    }
    if (lane == 0){
        g_rp[w] = sigf(s1 + br[0]);
        g_ap[w] = sigf(s2 + ba[0]);
    }
}

// ---- windowed attn + fused lc reduce: one block per (t,b), thread = s ----
__global__ void k_window_attn_lc(const float* __restrict__ at){
    const int blk = blockIdx.x;           // = t*BB + b
    const int t = blk / BB, b = blk % BB;
    const int s = threadIdx.x;
    const int lane = s & 31, warp = s >> 5;
    int k = min(t+1, HH);
    float acc = 0.f;
    for (int j = 0; j < k; j++)
        acc = fmaf(g_w[t][j], at[(size_t)(b*TT + (t-j))*SS + s], acc);
    g_attn_w[(size_t)blk*SS + s] = acc;
    float v = acc * g_eW2[b*SS + s];
    __shared__ float red[8];
    for (int o = 16; o; o >>= 1) v += __shfl_xor_sync(0xffffffffu, v, o);
    if (lane == 0) red[warp] = v;
    __syncthreads();
    if (warp == 0){
        float x = (lane < 8) ? red[lane] : 0.f;
        for (int o = 4; o; o >>= 1) x += __shfl_xor_sync(0xffffffffu, x, o);
        if (lane == 0) g_lc[blk] = x;
    }
}

// ---- tensor-core GEMM: G = q @ Wq, 8 warps x (32x64) tiles, cp.async 2-stage, occ 2 ----
// stage layout: 4 arrays (Ah|Al|Bh|Bl), each [128 rows][40 bf16] = 10240 B
#define GARR   10240
#define GSTAGE 40960
__global__ __launch_bounds__(256, 2) void k_gemm(){
    extern __shared__ __align__(16) unsigned char dsm[];
    const int tid = threadIdx.x;
    const int m0 = blockIdx.y * 128;
    const int n0 = blockIdx.x * 128;
    const int wid = tid >> 5, lane = tid & 31;
    const int wm = (wid & 3) * 32;
    const int wn = (wid >> 2) * 64;
    const int lr = tid >> 1;            // staging row 0..127
    const int lc0 = (tid & 1) * 16;     // cols {0,16}

    const int rsA = (lane & 7) + ((lane >> 3) & 1) * 8;
    const int kbA = ((lane >> 4) & 1) * 16;
    const int rsB = (lane & 7) + ((lane >> 4) & 1) * 8;
    const int kbB = ((lane >> 3) & 1) * 16;

    const uint32_t sbase = s2u(dsm);
    const uint32_t aH0 = sbase + (uint32_t)(wm + rsA)*80 + kbA;
    const uint32_t aL0 = aH0 + GARR;
    const uint32_t bH0 = sbase + 2*GARR + (uint32_t)(wn + rsB)*80 + kbB;
    const uint32_t bL0 = bH0 + GARR;

    const size_t aRow = (size_t)(m0 + lr)*DD;
    const size_t bRow = (size_t)(n0 + lr)*DD;
    const uint32_t stRow = sbase + (uint32_t)lr*80 + lc0*2;   // byte addr of this thread's 16B pair

    float acc[2][8][4] = {};

    // prologue: stage chunk 0 into buf 0  (each thread: 2x16B per array)
    #pragma unroll
    for (int j = 0; j < 2; j++){
        CP16(stRow          + j*16, &g_Ah[aRow + lc0 + j*8]);
        CP16(stRow +   GARR + j*16, &g_Al[aRow + lc0 + j*8]);
        CP16(stRow + 2*GARR + j*16, &g_BTh[bRow + lc0 + j*8]);
        CP16(stRow + 3*GARR + j*16, &g_BTl[bRow + lc0 + j*8]);
    }
    asm volatile("cp.async.commit_group;\n" ::: "memory");

    const int NIT = DD/32;
    for (int it = 0; it < NIT; it++){
        const uint32_t so = (uint32_t)(it & 1) * GSTAGE;
        if (it + 1 < NIT){
            const int k0 = (it+1)*32;
            const uint32_t sn = stRow + (uint32_t)((it+1) & 1) * GSTAGE;
            #pragma unroll
            for (int j = 0; j < 2; j++){
                CP16(sn          + j*16, &g_Ah[aRow + k0 + lc0 + j*8]);
                CP16(sn +   GARR + j*16, &g_Al[aRow + k0 + lc0 + j*8]);
                CP16(sn + 2*GARR + j*16, &g_BTh[bRow + k0 + lc0 + j*8]);
                CP16(sn + 3*GARR + j*16, &g_BTl[bRow + k0 + lc0 + j*8]);
            }
            asm volatile("cp.async.commit_group;\n" ::: "memory");
            asm volatile("cp.async.wait_group 1;\n" ::: "memory");
        } else {
            asm volatile("cp.async.wait_group 0;\n" ::: "memory");
        }
        __syncthreads();
        #pragma unroll
        for (int ks = 0; ks < 2; ks++){
            const int ksb = ks * 32;     // byte offset within 40-col row
            unsigned ah[2][4], al_[2][4];
            #pragma unroll
            for (int mt = 0; mt < 2; mt++){
                LDSM_X4(ah[mt],  aH0 + so + mt*16*80 + ksb);
                LDSM_X4(al_[mt], aL0 + so + mt*16*80 + ksb);
            }
            #pragma unroll
            for (int p = 0; p < 4; p++){
                unsigned bh[4], bl[4];
                LDSM_X4(bh, bH0 + so + p*16*80 + ksb);
                LDSM_X4(bl, bL0 + so + p*16*80 + ksb);
                #pragma unroll
                for (int mt = 0; mt < 2; mt++){
                    MMA_BF16(acc[mt][2*p],   ah[mt],  bh[0], bh[1]);
                    MMA_BF16(acc[mt][2*p],   ah[mt],  bl[0], bl[1]);
                    MMA_BF16(acc[mt][2*p],   al_[mt], bh[0], bh[1]);
                    MMA_BF16(acc[mt][2*p+1], ah[mt],  bh[2], bh[3]);
                    MMA_BF16(acc[mt][2*p+1], ah[mt],  bl[2], bl[3]);
                    MMA_BF16(acc[mt][2*p+1], al_[mt], bh[2], bh[3]);
                }
            }
        }
        __syncthreads();
    }
    const int lr4 = lane >> 2;
    const int lc2 = (lane & 3) * 2;
    #pragma unroll
    for (int mt = 0; mt < 2; mt++)
        #pragma unroll
        for (int nt = 0; nt < 8; nt++){
            int row = m0 + wm + mt*16 + lr4;
            int col = n0 + wn + nt*8 + lc2;
            #pragma unroll
            for (int rr = 0; rr < 2; rr++){
                float x = acc[mt][nt][rr*2], y = acc[mt][nt][rr*2+1];
                __nv_bfloat16 hx,lx,hy,ly;
                split1(x,hx,lx); split1(y,hy,ly);
                __nv_bfloat162 hh; hh.x=hx; hh.y=hy;
                __nv_bfloat162 ll; ll.x=lx; ll.y=ly;
                size_t o = (size_t)(row + rr*8)*DD + col;
                *(__nv_bfloat162*)&g_Gh[o] = hh;
                *(__nv_bfloat162*)&g_Gl[o] = ll;
            }
        }
}

// ---- tensor-core Eq0 + fused eW: per-b C[s,t] = e[b,s,:].G[b,t,:] ----
__global__ __launch_bounds__(256) void k_eq0(const float* __restrict__ e,
                                             const float* __restrict__ Wn){
    __shared__ __align__(16) __nv_bfloat16 sAh[64][72], sAl[64][72];
    __shared__ __align__(16) __nv_bfloat16 sBh[64][72], sBl[64][72];
    const int tid = threadIdx.x;
    const int b = blockIdx.y;
    const int s0 = blockIdx.x * 64;
    const int wid = tid >> 5, lane = tid & 31;
    const int wm = (wid & 1) * 32;
    const int wn = (wid >> 1) * 16;
    const int lr = tid >> 2;            // staging row 0..63
    const int kq = (tid & 3) * 16;      // k offset

    const int rsA = (lane & 7) + ((lane >> 3) & 1) * 8;
    const int kbA = ((lane >> 4) & 1) * 16;
    const int rsB = (lane & 7) + ((lane >> 4) & 1) * 8;
    const int kbB = ((lane >> 3) & 1) * 16;
    const uint32_t aH = s2u(&sAh[wm + rsA][0]) + kbA;
    const uint32_t aL = s2u(&sAl[wm + rsA][0]) + kbA;
    const uint32_t bH = s2u(&sBh[wn + rsB][0]) + kbB;
    const uint32_t bL = s2u(&sBl[wn + rsB][0]) + kbB;

    const size_t aRow = (size_t)(b*SS + s0 + lr)*DD;
    const bool bv = lr < TT;
    const size_t bRow = (size_t)(b*TT + (bv ? lr : 0))*DD;

    float acc[2][2][4] = {};
    float s1 = 0.f, s2 = 0.f;   // fused eW dots for row lr (partial over kq)

    for (int k0 = 0; k0 < DD; k0 += 64){
        float4 av[4];
        #pragma unroll
        for (int q4 = 0; q4 < 4; q4++){
            av[q4] = *(const float4*)&e[aRow + k0 + kq + q4*4];
            float4 w1 = *(const float4*)&Wn[k0 + kq + q4*4];
            float4 w2 = *(const float4*)&Wn[DD + k0 + kq + q4*4];
            s1 += av[q4].x*w1.x + av[q4].y*w1.y + av[q4].z*w1.z + av[q4].w*w1.w;
            s2 += av[q4].x*w2.x + av[q4].y*w2.y + av[q4].z*w2.z + av[q4].w*w2.w;
        }
        uint4 z = make_uint4(0,0,0,0);
        uint4 gh0 = bv ? *(const uint4*)&g_Gh[bRow + k0 + kq]     : z;
        uint4 gh1 = bv ? *(const uint4*)&g_Gh[bRow + k0 + kq + 8] : z;
        uint4 gl0 = bv ? *(const uint4*)&g_Gl[bRow + k0 + kq]     : z;
        uint4 gl1 = bv ? *(const uint4*)&g_Gl[bRow + k0 + kq + 8] : z;
        __syncthreads();
        #pragma unroll
        for (int q4 = 0; q4 < 4; q4++){
            float vv[4] = {av[q4].x, av[q4].y, av[q4].z, av[q4].w};
            #pragma unroll
            for (int u = 0; u < 4; u += 2){
                __nv_bfloat16 h0,l0,h1,l1;
                split1(vv[u],h0,l0); split1(vv[u+1],h1,l1);
                __nv_bfloat162 hh; hh.x=h0; hh.y=h1;
                __nv_bfloat162 ll; ll.x=l0; ll.y=l1;
                *(__nv_bfloat162*)&sAh[lr][kq + q4*4 + u] = hh;
                *(__nv_bfloat162*)&sAl[lr][kq + q4*4 + u] = ll;
            }
        }
        *(uint4*)&sBh[lr][kq]     = gh0;
        *(uint4*)&sBh[lr][kq + 8] = gh1;
        *(uint4*)&sBl[lr][kq]     = gl0;
        *(uint4*)&sBl[lr][kq + 8] = gl1;
        __syncthreads();
        #pragma unroll
        for (int ks = 0; ks < 64; ks += 16){
            const int ksb = ks * 2;
            unsigned ah[2][4], al_[2][4], bh[4], bl[4];
            LDSM_X4(ah[0],  aH + ksb);
            LDSM_X4(ah[1],  aH + 16*144 + ksb);
            LDSM_X4(al_[0], aL + ksb);
            LDSM_X4(al_[1], aL + 16*144 + ksb);
            LDSM_X4(bh, bH + ksb);
            LDSM_X4(bl, bL + ksb);
            #pragma unroll
            for (int mf = 0; mf < 2; mf++){
                MMA_BF16(acc[mf][0], ah[mf],  bh[0], bh[1]);
                MMA_BF16(acc[mf][0], ah[mf],  bl[0], bl[1]);
                MMA_BF16(acc[mf][0], al_[mf], bh[0], bh[1]);
                MMA_BF16(acc[mf][1], ah[mf],  bh[2], bh[3]);
                MMA_BF16(acc[mf][1], ah[mf],  bl[2], bl[3]);
                MMA_BF16(acc[mf][1], al_[mf], bh[2], bh[3]);
            }
        }
        __syncthreads();
    }
    // fused eW reduction: 4 threads share row lr (consecutive lanes)
    s1 += __shfl_xor_sync(0xffffffffu, s1, 1);
    s1 += __shfl_xor_sync(0xffffffffu, s1, 2);
    s2 += __shfl_xor_sync(0xffffffffu, s2, 1);
    s2 += __shfl_xor_sync(0xffffffffu, s2, 2);
    if ((tid & 3) == 0){
        g_eW1[b*SS + s0 + lr] = s1;
        g_eW2[b*SS + s0 + lr] = s2;
    }
    const int lr4 = lane >> 2;
    const int lc2 = (lane & 3) * 2;
    #pragma unroll
    for (int mf = 0; mf < 2; mf++)
        #pragma unroll
        for (int nf = 0; nf < 2; nf++){
            int s = s0 + wm + mf*16 + lr4;
            int t0 = wn + nf*8 + lc2;
            if (t0 < TT){
                g_Eq0[((size_t)t0*BB + b)*SS + s]       = acc[mf][nf][0];
                g_Eq0[((size_t)t0*BB + b)*SS + s + 8]   = acc[mf][nf][2];
            }
            if (t0 + 1 < TT){
                g_Eq0[((size_t)(t0+1)*BB + b)*SS + s]     = acc[mf][nf][1];
                g_Eq0[((size_t)(t0+1)*BB + b)*SS + s + 8] = acc[mf][nf][3];
            }
        }
}

// ---- 20-tap window over Eq0 -> Eq ----
__global__ void k_window_eq(){
    int idx = blockIdx.x*blockDim.x + threadIdx.x;
    if (idx >= TT*BB*SS) return;
    int s = idx % SS; int b = (idx / SS) % BB; int t = idx / (SS*BB);
    int k = min(t+1, HH);
    float acc = 0.f;
    for (int j = 0; j < k; j++)
        acc = fmaf(g_w[t][j], g_Eq0[((size_t)(t-j)*BB + b)*SS + s], acc);
    g_Eq[idx] = acc;
}

// ---- scalar recurrence; emits split+transposed sel weights [b][t][s] ----
__global__ void k_recur(const float* __restrict__ at, const float* __restrict__ bn){
    int idx = blockIdx.x*blockDim.x + threadIdx.x;
    if (idx >= BB*SS) return;
    const int b = idx / SS, s = idx % SS;
    float add0 = (s < 50) ? 1.f - (float)(s+1)*0.02f : 0.f;
    float g = add0, a = add0;
    const float ew1 = g_eW1[idx];
    const float bnv = bn[0];
    for (int t = 0; t < TT; t++){
        int base = (t*BB + b)*SS + s;
        float aw  = g_attn_w[base];
        float eq  = g_Eq[base];
        float atv = at[(size_t)(b*TT + t)*SS + s];
        float w = atv * g;                          // pre-update g
        __nv_bfloat16 h, l; split1(w, h, l);
        size_t wo = ((size_t)(b*64 + t))*SS + s;
        g_Wh[wo] = h; g_Wl[wo] = l;
        float rp = g_rp[t*BB + b], ap = g_ap[t*BB + b];
        float lc = g_lc[t*BB + b];
        float sim = sigf(g * eq);
        float nxt = sigf(ew1 + lc + bnv);
        float c2  = (1.f - a) * ap * nxt;
        g = g * (1.f - rp * aw * sim) + c2;
        a = a + c2;
    }
    __nv_bfloat16 zz = __float2bfloat16(0.f);
    for (int t = TT; t < 64; t++){
        size_t wo = ((size_t)(b*64 + t))*SS + s;
        g_Wh[wo] = zz; g_Wl[wo] = zz;
    }
}

// ---- tensor-core sel: per-b out[t,d] = sum_s W[t,s]*e[s,d] ----
__global__ __launch_bounds__(256) void k_sel(const float* __restrict__ e, float* __restrict__ out){
    __shared__ __align__(16) __nv_bfloat16 sWh[64][40], sWl[64][40];
    __shared__ __align__(16) __nv_bfloat16 sEh[128][40], sEl[128][40];
    const int tid = threadIdx.x;
    const int b = blockIdx.y;
    const int d0 = blockIdx.x * 128;
    const int wid = tid >> 5, lane = tid & 31;
    const int wm = (wid & 1) * 32;
    const int wn = (wid >> 1) * 32;
    // W staging (threads < 128): row wr, k group
    const int wr = tid >> 1, wkg = (tid & 1) * 16;
    // E staging (all 256): row er (s_local), col group cg
    const int er = tid & 31, cg = tid >> 5;

    const int rsA = (lane & 7) + ((lane >> 3) & 1) * 8;
    const int kbA = ((lane >> 4) & 1) * 16;
    const int rsB = (lane & 7) + ((lane >> 4) & 1) * 8;
    const int kbB = ((lane >> 3) & 1) * 16;
    const uint32_t aH = s2u(&sWh[wm + rsA][0]) + kbA;
    const uint32_t aL = s2u(&sWl[wm + rsA][0]) + kbA;
    const uint32_t bH = s2u(&sEh[wn + rsB][0]) + kbB;
    const uint32_t bL = s2u(&sEl[wn + rsB][0]) + kbB;

    float acc[2][4][4] = {};

    for (int s0 = 0; s0 < SS; s0 += 32){
        uint4 wv0, wv1, wl0, wl1;
        if (tid < 128){
            size_t o = ((size_t)(b*64 + wr))*SS + s0 + wkg;
            wv0 = *(const uint4*)&g_Wh[o];
            wv1 = *(const uint4*)&g_Wh[o + 8];
            wl0 = *(const uint4*)&g_Wl[o];
            wl1 = *(const uint4*)&g_Wl[o + 8];
        }
        float4 ev[4];
        #pragma unroll
        for (int q4 = 0; q4 < 4; q4++)
            ev[q4] = *(const float4*)&e[(size_t)(b*SS + s0 + er)*DD + d0 + cg*16 + q4*4];
        __syncthreads();
        if (tid < 128){
            *(uint4*)&sWh[wr][wkg]     = wv0;
            *(uint4*)&sWh[wr][wkg + 8] = wv1;
            *(uint4*)&sWl[wr][wkg]     = wl0;
            *(uint4*)&sWl[wr][wkg + 8] = wl1;
        }
        #pragma unroll
        for (int q4 = 0; q4 < 4; q4++){
            float vv[4] = {ev[q4].x, ev[q4].y, ev[q4].z, ev[q4].w};
            #pragma unroll
            for (int u = 0; u < 4; u++){
                __nv_bfloat16 h, l; split1(vv[u], h, l);
                int d_local = cg*16 + q4*4 + u;
                sEh[d_local][er] = h;
                sEl[d_local][er] = l;
            }
        }
        __syncthreads();
        #pragma unroll
        for (int ks = 0; ks < 32; ks += 16){
            const int ksb = ks * 2;
            unsigned ah[2][4], al_[2][4];
            LDSM_X4(ah[0],  aH + ksb);
            LDSM_X4(ah[1],  aH + 16*80 + ksb);
            LDSM_X4(al_[0], aL + ksb);
            LDSM_X4(al_[1], aL + 16*80 + ksb);
            #pragma unroll
            for (int p = 0; p < 2; p++){
                unsigned bh[4], bl[4];
                LDSM_X4(bh, bH + p*16*80 + ksb);
                LDSM_X4(bl, bL + p*16*80 + ksb);
                #pragma unroll
                for (int mf = 0; mf < 2; mf++){
                    MMA_BF16(acc[mf][2*p],   ah[mf],  bh[0], bh[1]);
                    MMA_BF16(acc[mf][2*p],   ah[mf],  bl[0], bl[1]);
                    MMA_BF16(acc[mf][2*p],   al_[mf], bh[0], bh[1]);
                    MMA_BF16(acc[mf][2*p+1], ah[mf],  bh[2], bh[3]);
                    MMA_BF16(acc[mf][2*p+1], ah[mf],  bl[2], bl[3]);
                    MMA_BF16(acc[mf][2*p+1], al_[mf], bh[2], bh[3]);
                }
            }
        }
        __syncthreads();
    }
    const int lr4 = lane >> 2;
    const int lc2 = (lane & 3) * 2;
    #pragma unroll
    for (int mf = 0; mf < 2; mf++)
        #pragma unroll
        for (int nf = 0; nf < 4; nf++){
            int d = d0 + wn + nf*8 + lc2;
            #pragma unroll
            for (int rr = 0; rr < 2; rr++){
                int t = wm + mf*16 + lr4 + rr*8;
                if (t < TT){
                    float2 v = make_float2(acc[mf][nf][rr*2], acc[mf][nf][rr*2+1]);
                    *(float2*)&out[((size_t)b*TT + t)*DD + d] = v;
                }
            }
        }
}

extern "C" void kernel_launch(void* const* d_in, const int* in_sizes, int n_in,
                              void* d_out, int out_size){
    const float* e  = (const float*)d_in[0];
    const float* q  = (const float*)d_in[1];
    const float* at = (const float*)d_in[2];
    const float* Wr = (const float*)d_in[3];
    const float* br = (const float*)d_in[4];
    const float* Wa = (const float*)d_in[5];
    const float* ba = (const float*)d_in[6];
    const float* Wq = (const float*)d_in[7];
    const float* Wn = (const float*)d_in[8];
    const float* bn = (const float*)d_in[9];
    float* out = (float*)d_out;

    static int smem_set = 0;
    if (!smem_set){
        cudaFuncSetAttribute(k_gemm, cudaFuncAttributeMaxDynamicSharedMemorySize, 2*GSTAGE);
        smem_set = 1;
    }

    k_weights<<<1, 64>>>();
    { dim3 gw(32, 32); k_split_Wq<<<gw, dim3(32, 8)>>>(Wq); }
    k_gates<<<(TT*BB*32 + 255)/256, 256>>>(q, Wr, br, Wa, ba);
    { dim3 gg(DD/128, MTOT/128); k_gemm<<<gg, 256, 2*GSTAGE>>>(); }
    { dim3 ge(SS/64, BB);        k_eq0<<<ge, 256>>>(e, Wn); }
    k_window_attn_lc<<<TT*BB, SS>>>(at);
    k_window_eq<<<(TT*BB*SS + 255)/256, 256>>>();
    k_recur<<<(BB*SS + 255)/256, 256>>>(at, bn);
    { dim3 gs(DD/128, BB);       k_sel<<<gs, 256>>>(e, out); }
}

// round 13
// speedup vs baseline: 1.2701x; 1.1442x over previous
#include <cuda_runtime.h>
#include <cuda_bf16.h>
#include <cstdint>
#include <math.h>

#define TT 60
#define BB 64
#define SS 256
#define DD 1024
#define HH 20
#define MTOT (BB*TT)   // 3840 rows of q

// ---- scratch (static device globals) ----
__device__ float g_w[TT][HH];                    // history softmax weights
__device__ float g_attn_w[TT*BB*SS];             // windowed attention [(t*B+b)*S+s]
// packed, pre-swizzled GEMM operands:
//   g_A2[mblk][chunk][2(h/l)][4096 elems]  (16KB per (mblk,chunk))
//   g_B2[nblk][chunk][2(h/l)][4096 elems]
__device__ __align__(16) __nv_bfloat16 g_A2[30*32*8192];
__device__ __align__(16) __nv_bfloat16 g_B2[8*32*8192];
__device__ __nv_bfloat16 g_Gh[MTOT*DD];          // (q@Wq) split hi [m][d]
__device__ __nv_bfloat16 g_Gl[MTOT*DD];          // (q@Wq) split lo
__device__ float g_Eq0[TT*BB*SS];                // e . (qWq)  [(t*B+b)*S+s]
__device__ float g_Eq[TT*BB*SS];                 // windowed Eq0
__device__ float g_rp[TT*BB];                    // remove_prob
__device__ float g_ap[TT*BB];                    // add_prob
__device__ float g_lc[TT*BB];                    // sum_s attn_w*eW2
__device__ float g_eW1[BB*SS];                   // e . Wn[:D]
__device__ float g_eW2[BB*SS];                   // e . Wn[D:]
__device__ __nv_bfloat16 g_Wh[BB*64*SS];         // sel weights split hi [b][t(pad64)][s]
__device__ __nv_bfloat16 g_Wl[BB*64*SS];         // sel weights split lo

__device__ __forceinline__ float sigf(float x){ return 1.0f/(1.0f+expf(-x)); }
__device__ __forceinline__ void split1(float x, __nv_bfloat16& h, __nv_bfloat16& l){
    h = __float2bfloat16(x);
    l = __float2bfloat16(x - __bfloat162float(h));
}
__device__ __forceinline__ uint32_t s2u(const void* p){
    return (uint32_t)__cvta_generic_to_shared(p);
}

#define MMA_BF16(d, a, b0, b1) asm volatile( \
  "mma.sync.aligned.m16n8k16.row.col.f32.bf16.bf16.f32 " \
  "{%0,%1,%2,%3},{%4,%5,%6,%7},{%8,%9},{%0,%1,%2,%3};\n" \
  : "+f"(d[0]), "+f"(d[1]), "+f"(d[2]), "+f"(d[3]) \
  : "r"(a[0]), "r"(a[1]), "r"(a[2]), "r"(a[3]), "r"(b0), "r"(b1))

#define LDSM_X4(r, addr) asm volatile( \
  "ldmatrix.sync.aligned.m8n8.x4.shared.b16 {%0,%1,%2,%3},[%4];\n" \
  : "=r"((r)[0]), "=r"((r)[1]), "=r"((r)[2]), "=r"((r)[3]) : "r"(addr))

__device__ __forceinline__ void mbar_init(uint32_t addr, uint32_t cnt){
    asm volatile("mbarrier.init.shared.b64 [%0], %1;" :: "r"(addr), "r"(cnt) : "memory");
}
__device__ __forceinline__ void mbar_expect_tx(uint32_t addr, uint32_t bytes){
    asm volatile("mbarrier.arrive.expect_tx.shared.b64 _, [%0], %1;" :: "r"(addr), "r"(bytes) : "memory");
}
__device__ __forceinline__ void mbar_wait(uint32_t addr, uint32_t parity){
    asm volatile(
      "{\n\t.reg .pred P;\n"
      "W%=:\n\t"
      "mbarrier.try_wait.parity.acquire.cta.shared::cta.b64 P, [%0], %1, 0x989680;\n\t"
      "@!P bra W%=;\n\t}"
      :: "r"(addr), "r"(parity) : "memory");
}
__device__ __forceinline__ void bulk_g2s(uint32_t dst, const void* src, uint32_t bytes, uint32_t mbar){
    asm volatile("cp.async.bulk.shared::cta.global.mbarrier::complete_tx::bytes [%0], [%1], %2, [%3];\n"
                 :: "r"(dst), "l"(src), "r"(bytes), "r"(mbar) : "memory");
}

// ---- step-weight table ----
__global__ void k_weights(){
    int i = threadIdx.x;
    if (i >= TT) return;
    int k = min(i+1, HH);
    float Z = 0.f;
    for (int j = 0; j < k; j++) Z += expf((20.f - (float)j) / 20.f);
    for (int j = 0; j < HH; j++)
        g_w[i][j] = (j < k) ? expf((20.f - (float)j) / 20.f) / Z : 0.f;
}

// ---- transpose + split Wq into packed swizzled tiles g_B2 ----
__global__ void k_split_Wq(const float* __restrict__ Wq){
    __shared__ float tile[32][33];
    int k0 = blockIdx.y*32, n0 = blockIdx.x*32;
    int tx = threadIdx.x, ty = threadIdx.y;  // (32,8)
    #pragma unroll
    for (int i = 0; i < 32; i += 8)
        tile[ty+i][tx] = Wq[(size_t)(k0+ty+i)*DD + n0+tx];
    __syncthreads();
    const int chunk = k0 >> 5;
    #pragma unroll
    for (int i = 0; i < 32; i += 8){
        float x = tile[tx][ty+i];
        __nv_bfloat16 h, l; split1(x, h, l);
        int n = n0 + ty + i;
        int r = n & 127, nblk = n >> 7;
        int su = (tx >> 3) ^ ((r >> 1) & 3);
        size_t base = ((size_t)(nblk*32 + chunk))*8192 + r*32 + su*8 + (tx & 7);
        g_B2[base]        = h;
        g_B2[base + 4096] = l;
    }
}

// ---- gates rp/ap[t,b] + q bf16 split into packed swizzled tiles g_A2 ----
__global__ void k_gates(const float* __restrict__ q, const float* __restrict__ Wr,
                        const float* __restrict__ br, const float* __restrict__ Wa,
                        const float* __restrict__ ba){
    int w = (blockIdx.x*blockDim.x + threadIdx.x) >> 5;
    int lane = threadIdx.x & 31;
    if (w >= TT*BB) return;
    int t = w / BB, b = w % BB;
    const int m = b*TT + t;
    const int r = m & 127, mblk = m >> 7, xorv = (r >> 1) & 3;
    const float* qr = q + (size_t)m*DD;
    float s1 = 0.f, s2 = 0.f;
    for (int d = lane*4; d < DD; d += 128){
        float4 qv = *(const float4*)(qr + d);
        float4 r4 = *(const float4*)(Wr + d);
        float4 a4 = *(const float4*)(Wa + d);
        s1 += qv.x*r4.x + qv.y*r4.y + qv.z*r4.z + qv.w*r4.w;
        s2 += qv.x*a4.x + qv.y*a4.y + qv.z*a4.z + qv.w*a4.w;
        __nv_bfloat16 h0,l0,h1,l1,h2,l2,h3,l3;
        split1(qv.x,h0,l0); split1(qv.y,h1,l1); split1(qv.z,h2,l2); split1(qv.w,h3,l3);
        __nv_bfloat162 hh0; hh0.x=h0; hh0.y=h1;
        __nv_bfloat162 hh1; hh1.x=h2; hh1.y=h3;
        __nv_bfloat162 ll0; ll0.x=l0; ll0.y=l1;
        __nv_bfloat162 ll1; ll1.x=l2; ll1.y=l3;
        int chunk = d >> 5, kk = d & 31;
        int su = (kk >> 3) ^ xorv;
        size_t base = ((size_t)(mblk*32 + chunk))*8192 + r*32 + su*8 + (kk & 7);
        *(__nv_bfloat162*)&g_A2[base]          = hh0;
        *(__nv_bfloat162*)&g_A2[base + 2]      = hh1;
        *(__nv_bfloat162*)&g_A2[base + 4096]   = ll0;
        *(__nv_bfloat162*)&g_A2[base + 4098]   = ll1;
    }
    for (int o = 16; o; o >>= 1){
        s1 += __shfl_xor_sync(0xffffffffu, s1, o);
        s2 += __shfl_xor_sync(0xffffffffu, s2, o);
    }
    if (lane == 0){
        g_rp[w] = sigf(s1 + br[0]);
        g_ap[w] = sigf(s2 + ba[0]);
    }
}

// ---- windowed attn + fused lc reduce: one block per (t,b), thread = s ----
__global__ void k_window_attn_lc(const float* __restrict__ at){
    const int blk = blockIdx.x;           // = t*BB + b
    const int t = blk / BB, b = blk % BB;
    const int s = threadIdx.x;
    const int lane = s & 31, warp = s >> 5;
    int k = min(t+1, HH);
    float acc = 0.f;
    for (int j = 0; j < k; j++)
        acc = fmaf(g_w[t][j], at[(size_t)(b*TT + (t-j))*SS + s], acc);
    g_attn_w[(size_t)blk*SS + s] = acc;
    float v = acc * g_eW2[b*SS + s];
    __shared__ float red[8];
    for (int o = 16; o; o >>= 1) v += __shfl_xor_sync(0xffffffffu, v, o);
    if (lane == 0) red[warp] = v;
    __syncthreads();
    if (warp == 0){
        float x = (lane < 8) ? red[lane] : 0.f;
        for (int o = 4; o; o >>= 1) x += __shfl_xor_sync(0xffffffffu, x, o);
        if (lane == 0) g_lc[blk] = x;
    }
}

// ---- tensor-core GEMM: G = q@Wq, cp.async.bulk 3-stage, 8 warps x (32x64) ----
#define NST 3
#define STB 32768          // bytes per stage: [Ah 8K][Al 8K][Bh 8K][Bl 8K]
__global__ __launch_bounds__(256) void k_gemm(){
    extern __shared__ __align__(1024) unsigned char dsm[];
    __shared__ __align__(8) uint64_t s_mb[NST];
    const int tid = threadIdx.x;
    const int mblk = blockIdx.y;    // 0..29
    const int nblk = blockIdx.x;    // 0..7
    const int wid = tid >> 5, lane = tid & 31;
    const int wm = (wid & 3) * 32;
    const int wn = (wid >> 2) * 64;
    const uint32_t sb = s2u(dsm);

    // ldsm row/unit selectors
    const int uAsel = (lane >> 4) & 1;
    const int uBsel = (lane >> 3) & 1;
    int rA[2], xA[2];
    #pragma unroll
    for (int mt = 0; mt < 2; mt++){
        rA[mt] = wm + (lane & 7) + ((lane >> 3) & 1) * 8 + mt*16;
        xA[mt] = (rA[mt] >> 1) & 3;
    }
    int rB[4], xB[4];
    #pragma unroll
    for (int p = 0; p < 4; p++){
        rB[p] = wn + (lane & 7) + ((lane >> 4) & 1) * 8 + p*16;
        xB[p] = (rB[p] >> 1) & 3;
    }

    if (tid == 0){
        #pragma unroll
        for (int s = 0; s < NST; s++) mbar_init(s2u(&s_mb[s]), 1);
    }
    __syncthreads();

    const __nv_bfloat16* srcA = &g_A2[((size_t)mblk*32)*8192];
    const __nv_bfloat16* srcB = &g_B2[((size_t)nblk*32)*8192];

    // prologue: issue chunks 0,1
    if (tid == 0){
        #pragma unroll
        for (int c = 0; c < 2; c++){
            uint32_t mb = s2u(&s_mb[c]);
            uint32_t st = sb + c*STB;
            mbar_expect_tx(mb, 32768);
            bulk_g2s(st,          srcA + (size_t)c*8192, 16384, mb);
            bulk_g2s(st + 16384,  srcB + (size_t)c*8192, 16384, mb);
        }
    }

    float acc[2][8][4] = {};

    for (int c = 0; c < 32; c++){
        const int buf = c % 3;
        if (tid == 0 && c + 2 < 32){
            const int nb = (c + 2) % 3;
            uint32_t mb = s2u(&s_mb[nb]);
            uint32_t st = sb + nb*STB;
            mbar_expect_tx(mb, 32768);
            bulk_g2s(st,          srcA + (size_t)(c+2)*8192, 16384, mb);
            bulk_g2s(st + 16384,  srcB + (size_t)(c+2)*8192, 16384, mb);
        }
        mbar_wait(s2u(&s_mb[buf]), (uint32_t)((c/3) & 1));
        const uint32_t st = sb + (uint32_t)buf*STB;
        #pragma unroll
        for (int ks = 0; ks < 2; ks++){
            const int ubase = ks*2;
            unsigned ah[2][4], al_[2][4];
            #pragma unroll
            for (int mt = 0; mt < 2; mt++){
                uint32_t ro = st + (uint32_t)rA[mt]*64;
                uint32_t su = (uint32_t)(((ubase + uAsel) ^ xA[mt]) << 4);
                LDSM_X4(ah[mt],  ro + su);
                LDSM_X4(al_[mt], ro + su + 8192);
            }
            #pragma unroll
            for (int p = 0; p < 4; p++){
                unsigned bh[4], bl[4];
                uint32_t ro = st + 16384 + (uint32_t)rB[p]*64;
                uint32_t su = (uint32_t)(((ubase + uBsel) ^ xB[p]) << 4);
                LDSM_X4(bh, ro + su);
                LDSM_X4(bl, ro + su + 8192);
                #pragma unroll
                for (int mt = 0; mt < 2; mt++){
                    MMA_BF16(acc[mt][2*p],   ah[mt],  bh[0], bh[1]);
                    MMA_BF16(acc[mt][2*p],   ah[mt],  bl[0], bl[1]);
                    MMA_BF16(acc[mt][2*p],   al_[mt], bh[0], bh[1]);
                    MMA_BF16(acc[mt][2*p+1], ah[mt],  bh[2], bh[3]);
                    MMA_BF16(acc[mt][2*p+1], ah[mt],  bl[2], bl[3]);
                    MMA_BF16(acc[mt][2*p+1], al_[mt], bh[2], bh[3]);
                }
            }
        }
        __syncthreads();
    }
    const int lr4 = lane >> 2;
    const int lc2 = (lane & 3) * 2;
    const int m0 = mblk * 128, n0 = nblk * 128;
    #pragma unroll
    for (int mt = 0; mt < 2; mt++)
        #pragma unroll
        for (int nt = 0; nt < 8; nt++){
            int row = m0 + wm + mt*16 + lr4;
            int col = n0 + wn + nt*8 + lc2;
            #pragma unroll
            for (int rr = 0; rr < 2; rr++){
                float x = acc[mt][nt][rr*2], y = acc[mt][nt][rr*2+1];
                __nv_bfloat16 hx,lx,hy,ly;
                split1(x,hx,lx); split1(y,hy,ly);
                __nv_bfloat162 hh; hh.x=hx; hh.y=hy;
                __nv_bfloat162 ll; ll.x=lx; ll.y=ly;
                size_t o = (size_t)(row + rr*8)*DD + col;
                *(__nv_bfloat162*)&g_Gh[o] = hh;
                *(__nv_bfloat162*)&g_Gl[o] = ll;
            }
        }
}

// ---- tensor-core Eq0 + fused eW: per-b C[s,t] = e[b,s,:].G[b,t,:] ----
__global__ __launch_bounds__(256) void k_eq0(const float* __restrict__ e,
                                             const float* __restrict__ Wn){
    __shared__ __align__(16) __nv_bfloat16 sAh[64][72], sAl[64][72];
    __shared__ __align__(16) __nv_bfloat16 sBh[64][72], sBl[64][72];
    const int tid = threadIdx.x;
    const int b = blockIdx.y;
    const int s0 = blockIdx.x * 64;
    const int wid = tid >> 5, lane = tid & 31;
    const int wm = (wid & 1) * 32;
    const int wn = (wid >> 1) * 16;
    const int lr = tid >> 2;            // staging row 0..63
    const int kq = (tid & 3) * 16;      // k offset

    const int rsA = (lane & 7) + ((lane >> 3) & 1) * 8;
    const int kbA = ((lane >> 4) & 1) * 16;
    const int rsB = (lane & 7) + ((lane >> 4) & 1) * 8;
    const int kbB = ((lane >> 3) & 1) * 16;
    const uint32_t aH = s2u(&sAh[wm + rsA][0]) + kbA;
    const uint32_t aL = s2u(&sAl[wm + rsA][0]) + kbA;
    const uint32_t bH = s2u(&sBh[wn + rsB][0]) + kbB;
    const uint32_t bL = s2u(&sBl[wn + rsB][0]) + kbB;

    const size_t aRow = (size_t)(b*SS + s0 + lr)*DD;
    const bool bv = lr < TT;
    const size_t bRow = (size_t)(b*TT + (bv ? lr : 0))*DD;

    float acc[2][2][4] = {};
    float s1 = 0.f, s2 = 0.f;   // fused eW dots for row lr (partial over kq)

    for (int k0 = 0; k0 < DD; k0 += 64){
        float4 av[4];
        #pragma unroll
        for (int q4 = 0; q4 < 4; q4++){
            av[q4] = *(const float4*)&e[aRow + k0 + kq + q4*4];
            float4 w1 = *(const float4*)&Wn[k0 + kq + q4*4];
            float4 w2 = *(const float4*)&Wn[DD + k0 + kq + q4*4];
            s1 += av[q4].x*w1.x + av[q4].y*w1.y + av[q4].z*w1.z + av[q4].w*w1.w;
            s2 += av[q4].x*w2.x + av[q4].y*w2.y + av[q4].z*w2.z + av[q4].w*w2.w;
        }
        uint4 z = make_uint4(0,0,0,0);
        uint4 gh0 = bv ? *(const uint4*)&g_Gh[bRow + k0 + kq]     : z;
        uint4 gh1 = bv ? *(const uint4*)&g_Gh[bRow + k0 + kq + 8] : z;
        uint4 gl0 = bv ? *(const uint4*)&g_Gl[bRow + k0 + kq]     : z;
        uint4 gl1 = bv ? *(const uint4*)&g_Gl[bRow + k0 + kq + 8] : z;
        __syncthreads();
        #pragma unroll
        for (int q4 = 0; q4 < 4; q4++){
            float vv[4] = {av[q4].x, av[q4].y, av[q4].z, av[q4].w};
            #pragma unroll
            for (int u = 0; u < 4; u += 2){
                __nv_bfloat16 h0,l0,h1,l1;
                split1(vv[u],h0,l0); split1(vv[u+1],h1,l1);
                __nv_bfloat162 hh; hh.x=h0; hh.y=h1;
                __nv_bfloat162 ll; ll.x=l0; ll.y=l1;
                *(__nv_bfloat162*)&sAh[lr][kq + q4*4 + u] = hh;
                *(__nv_bfloat162*)&sAl[lr][kq + q4*4 + u] = ll;
            }
        }
        *(uint4*)&sBh[lr][kq]     = gh0;
        *(uint4*)&sBh[lr][kq + 8] = gh1;
        *(uint4*)&sBl[lr][kq]     = gl0;
        *(uint4*)&sBl[lr][kq + 8] = gl1;
        __syncthreads();
        #pragma unroll
        for (int ks = 0; ks < 64; ks += 16){
            const int ksb = ks * 2;
            unsigned ah[2][4], al_[2][4], bh[4], bl[4];
            LDSM_X4(ah[0],  aH + ksb);
            LDSM_X4(ah[1],  aH + 16*144 + ksb);
            LDSM_X4(al_[0], aL + ksb);
            LDSM_X4(al_[1], aL + 16*144 + ksb);
            LDSM_X4(bh, bH + ksb);
            LDSM_X4(bl, bL + ksb);
            #pragma unroll
            for (int mf = 0; mf < 2; mf++){
                MMA_BF16(acc[mf][0], ah[mf],  bh[0], bh[1]);
                MMA_BF16(acc[mf][0], ah[mf],  bl[0], bl[1]);
                MMA_BF16(acc[mf][0], al_[mf], bh[0], bh[1]);
                MMA_BF16(acc[mf][1], ah[mf],  bh[2], bh[3]);
                MMA_BF16(acc[mf][1], ah[mf],  bl[2], bl[3]);
                MMA_BF16(acc[mf][1], al_[mf], bh[2], bh[3]);
            }
        }
        __syncthreads();
    }
    // fused eW reduction: 4 threads share row lr (consecutive lanes)
    s1 += __shfl_xor_sync(0xffffffffu, s1, 1);
    s1 += __shfl_xor_sync(0xffffffffu, s1, 2);
    s2 += __shfl_xor_sync(0xffffffffu, s2, 1);
    s2 += __shfl_xor_sync(0xffffffffu, s2, 2);
    if ((tid & 3) == 0){
        g_eW1[b*SS + s0 + lr] = s1;
        g_eW2[b*SS + s0 + lr] = s2;
    }
    const int lr4 = lane >> 2;
    const int lc2 = (lane & 3) * 2;
    #pragma unroll
    for (int mf = 0; mf < 2; mf++)
        #pragma unroll
        for (int nf = 0; nf < 2; nf++){
            int s = s0 + wm + mf*16 + lr4;
            int t0 = wn + nf*8 + lc2;
            if (t0 < TT){
                g_Eq0[((size_t)t0*BB + b)*SS + s]       = acc[mf][nf][0];
                g_Eq0[((size_t)t0*BB + b)*SS + s + 8]   = acc[mf][nf][2];
            }
            if (t0 + 1 < TT){
                g_Eq0[((size_t)(t0+1)*BB + b)*SS + s]     = acc[mf][nf][1];
                g_Eq0[((size_t)(t0+1)*BB + b)*SS + s + 8] = acc[mf][nf][3];
            }
        }
}

// ---- 20-tap window over Eq0 -> Eq ----
__global__ void k_window_eq(){
    int idx = blockIdx.x*blockDim.x + threadIdx.x;
    if (idx >= TT*BB*SS) return;
    int s = idx % SS; int b = (idx / SS) % BB; int t = idx / (SS*BB);
    int k = min(t+1, HH);
    float acc = 0.f;
    for (int j = 0; j < k; j++)
        acc = fmaf(g_w[t][j], g_Eq0[((size_t)(t-j)*BB + b)*SS + s], acc);
    g_Eq[idx] = acc;
}

// ---- scalar recurrence; emits split+transposed sel weights [b][t][s] ----
__global__ void k_recur(const float* __restrict__ at, const float* __restrict__ bn){
    int idx = blockIdx.x*blockDim.x + threadIdx.x;
    if (idx >= BB*SS) return;
    const int b = idx / SS, s = idx % SS;
    float add0 = (s < 50) ? 1.f - (float)(s+1)*0.02f : 0.f;
    float g = add0, a = add0;
    const float ew1 = g_eW1[idx];
    const float bnv = bn[0];
    for (int t = 0; t < TT; t++){
        int base = (t*BB + b)*SS + s;
        float aw  = g_attn_w[base];
        float eq  = g_Eq[base];
        float atv = at[(size_t)(b*TT + t)*SS + s];
        float w = atv * g;                          // pre-update g
        __nv_bfloat16 h, l; split1(w, h, l);
        size_t wo = ((size_t)(b*64 + t))*SS + s;
        g_Wh[wo] = h; g_Wl[wo] = l;
        float rp = g_rp[t*BB + b], ap = g_ap[t*BB + b];
        float lc = g_lc[t*BB + b];
        float sim = sigf(g * eq);
        float nxt = sigf(ew1 + lc + bnv);
        float c2  = (1.f - a) * ap * nxt;
        g = g * (1.f - rp * aw * sim) + c2;
        a = a + c2;
    }
    __nv_bfloat16 zz = __float2bfloat16(0.f);
    for (int t = TT; t < 64; t++){
        size_t wo = ((size_t)(b*64 + t))*SS + s;
        g_Wh[wo] = zz; g_Wl[wo] = zz;
    }
}

// ---- tensor-core sel: per-b out[t,d] = sum_s W[t,s]*e[s,d] ----
__global__ __launch_bounds__(256) void k_sel(const float* __restrict__ e, float* __restrict__ out){
    __shared__ __align__(16) __nv_bfloat16 sWh[64][40], sWl[64][40];
    __shared__ __align__(16) __nv_bfloat16 sEh[128][40], sEl[128][40];
    const int tid = threadIdx.x;
    const int b = blockIdx.y;
    const int d0 = blockIdx.x * 128;
    const int wid = tid >> 5, lane = tid & 31;
    const int wm = (wid & 1) * 32;
    const int wn = (wid >> 1) * 32;
    // W staging (threads < 128): row wr, k group
    const int wr = tid >> 1, wkg = (tid & 1) * 16;
    // E staging (all 256): row er (s_local), col group cg
    const int er = tid & 31, cg = tid >> 5;

    const int rsA = (lane & 7) + ((lane >> 3) & 1) * 8;
    const int kbA = ((lane >> 4) & 1) * 16;
    const int rsB = (lane & 7) + ((lane >> 4) & 1) * 8;
    const int kbB = ((lane >> 3) & 1) * 16;
    const uint32_t aH = s2u(&sWh[wm + rsA][0]) + kbA;
    const uint32_t aL = s2u(&sWl[wm + rsA][0]) + kbA;
    const uint32_t bH = s2u(&sEh[wn + rsB][0]) + kbB;
    const uint32_t bL = s2u(&sEl[wn + rsB][0]) + kbB;

    float acc[2][4][4] = {};

    for (int s0 = 0; s0 < SS; s0 += 32){
        uint4 wv0, wv1, wl0, wl1;
        if (tid < 128){
            size_t o = ((size_t)(b*64 + wr))*SS + s0 + wkg;
            wv0 = *(const uint4*)&g_Wh[o];
            wv1 = *(const uint4*)&g_Wh[o + 8];
            wl0 = *(const uint4*)&g_Wl[o];
            wl1 = *(const uint4*)&g_Wl[o + 8];
        }
        float4 ev[4];
        #pragma unroll
        for (int q4 = 0; q4 < 4; q4++)
            ev[q4] = *(const float4*)&e[(size_t)(b*SS + s0 + er)*DD + d0 + cg*16 + q4*4];
        __syncthreads();
        if (tid < 128){
            *(uint4*)&sWh[wr][wkg]     = wv0;
            *(uint4*)&sWh[wr][wkg + 8] = wv1;
            *(uint4*)&sWl[wr][wkg]     = wl0;
            *(uint4*)&sWl[wr][wkg + 8] = wl1;
        }
        #pragma unroll
        for (int q4 = 0; q4 < 4; q4++){
            float vv[4] = {ev[q4].x, ev[q4].y, ev[q4].z, ev[q4].w};
            #pragma unroll
            for (int u = 0; u < 4; u++){
                __nv_bfloat16 h, l; split1(vv[u], h, l);
                int d_local = cg*16 + q4*4 + u;
                sEh[d_local][er] = h;
                sEl[d_local][er] = l;
            }
        }
        __syncthreads();
        #pragma unroll
        for (int ks = 0; ks < 32; ks += 16){
            const int ksb = ks * 2;
            unsigned ah[2][4], al_[2][4];
            LDSM_X4(ah[0],  aH + ksb);
            LDSM_X4(ah[1],  aH + 16*80 + ksb);
            LDSM_X4(al_[0], aL + ksb);
            LDSM_X4(al_[1], aL + 16*80 + ksb);
            #pragma unroll
            for (int p = 0; p < 2; p++){
                unsigned bh[4], bl[4];
                LDSM_X4(bh, bH + p*16*80 + ksb);
                LDSM_X4(bl, bL + p*16*80 + ksb);
                #pragma unroll
                for (int mf = 0; mf < 2; mf++){
                    MMA_BF16(acc[mf][2*p],   ah[mf],  bh[0], bh[1]);
                    MMA_BF16(acc[mf][2*p],   ah[mf],  bl[0], bl[1]);
                    MMA_BF16(acc[mf][2*p],   al_[mf], bh[0], bh[1]);
                    MMA_BF16(acc[mf][2*p+1], ah[mf],  bh[2], bh[3]);
                    MMA_BF16(acc[mf][2*p+1], ah[mf],  bl[2], bl[3]);
                    MMA_BF16(acc[mf][2*p+1], al_[mf], bh[2], bh[3]);
                }
            }
        }
        __syncthreads();
    }
    const int lr4 = lane >> 2;
    const int lc2 = (lane & 3) * 2;
    #pragma unroll
    for (int mf = 0; mf < 2; mf++)
        #pragma unroll
        for (int nf = 0; nf < 4; nf++){
            int d = d0 + wn + nf*8 + lc2;
            #pragma unroll
            for (int rr = 0; rr < 2; rr++){
                int t = wm + mf*16 + lr4 + rr*8;
                if (t < TT){
                    float2 v = make_float2(acc[mf][nf][rr*2], acc[mf][nf][rr*2+1]);
                    *(float2*)&out[((size_t)b*TT + t)*DD + d] = v;
                }
            }
        }
}

extern "C" void kernel_launch(void* const* d_in, const int* in_sizes, int n_in,
                              void* d_out, int out_size){
    const float* e  = (const float*)d_in[0];
    const float* q  = (const float*)d_in[1];
    const float* at = (const float*)d_in[2];
    const float* Wr = (const float*)d_in[3];
    const float* br = (const float*)d_in[4];
    const float* Wa = (const float*)d_in[5];
    const float* ba = (const float*)d_in[6];
    const float* Wq = (const float*)d_in[7];
    const float* Wn = (const float*)d_in[8];
    const float* bn = (const float*)d_in[9];
    float* out = (float*)d_out;

    const int gemm_dsm = NST*STB;   // 98304
    static int smem_set = 0;
    if (!smem_set){
        cudaFuncSetAttribute(k_gemm, cudaFuncAttributeMaxDynamicSharedMemorySize, gemm_dsm);
        smem_set = 1;
    }

    k_weights<<<1, 64>>>();
    { dim3 gw(32, 32); k_split_Wq<<<gw, dim3(32, 8)>>>(Wq); }
    k_gates<<<(TT*BB*32 + 255)/256, 256>>>(q, Wr, br, Wa, ba);
    { dim3 gg(DD/128, MTOT/128); k_gemm<<<gg, 256, gemm_dsm>>>(); }
    { dim3 ge(SS/64, BB);        k_eq0<<<ge, 256>>>(e, Wn); }
    k_window_attn_lc<<<TT*BB, SS>>>(at);
    k_window_eq<<<(TT*BB*SS + 255)/256, 256>>>();
    k_recur<<<(BB*SS + 255)/256, 256>>>(at, bn);
    { dim3 gs(DD/128, BB);       k_sel<<<gs, 256>>>(e, out); }
}